// round 3
// baseline (speedup 1.0000x reference)
#include <cuda_runtime.h>

#define HID   512
#define BATCH 256
#define TLEN  1024
#define GRID  256
#define NTHR  256
#define UNITS 2          // hidden units per block per layer (256*2 = 512)

// Persistent device state. h stored DUPLICATED as float2{v,v} so a single
// LDG.64 yields a ready-made f32x2 operand (no per-k pack mov).
__device__ unsigned long long g_h1[2][HID * BATCH];   // [k][b] packed pairs
__device__ unsigned long long g_h2[2][HID * BATCH];
__device__ float g_xT[TLEN * BATCH];                  // x transposed to [t][b]
__device__ unsigned long long g_epoch;
__device__ unsigned g_cnt;

__device__ __forceinline__ float sigm(float v) {
    return 1.0f / (1.0f + __expf(-v));
}

// ---- f32x2 packed-math helpers (Blackwell FFMA2 path) ----
__device__ __forceinline__ unsigned long long pack2(float lo, float hi) {
    unsigned long long r;
    asm("mov.b64 %0, {%1, %2};" : "=l"(r) : "f"(lo), "f"(hi));
    return r;
}
__device__ __forceinline__ void unpack2(unsigned long long v, float& lo, float& hi) {
    asm("mov.b64 {%0, %1}, %2;" : "=f"(lo), "=f"(hi) : "l"(v));
}
__device__ __forceinline__ unsigned long long fma2(unsigned long long a,
                                                   unsigned long long b,
                                                   unsigned long long c) {
    unsigned long long d;
    asm("fma.rn.f32x2 %0, %1, %2, %3;" : "=l"(d) : "l"(a), "l"(b), "l"(c));
    return d;
}

// Grid-wide barrier: 256 blocks, 2 blocks/SM co-resident (guaranteed by
// launch_bounds reg cap + 51KB smem/block; 256 <= 2*148).
__device__ __forceinline__ void grid_bar(unsigned long long& target) {
    __threadfence();          // release
    __syncthreads();
    if (threadIdx.x == 0) {
        target += 1;
        unsigned prev = atomicAdd(&g_cnt, 1u);
        if (prev == GRID - 1) {
            g_cnt = 0;
            __threadfence();
            atomicAdd(&g_epoch, 1ull);
        } else {
            while (*((volatile unsigned long long*)&g_epoch) < target) { }
        }
        __threadfence();      // acquire
    }
    __syncthreads();
}

// 4 packed FMAs: acc[j] covers gate rows (2j, 2j+1) of this block's 2 units.
#define FMA2x4(ACC, HV2, WB)                                         \
    do {                                                             \
        ulonglong2 q0_ = (WB)[0], q1_ = (WB)[1];                     \
        ACC[0] = fma2(q0_.x, (HV2), ACC[0]);                         \
        ACC[1] = fma2(q0_.y, (HV2), ACC[1]);                         \
        ACC[2] = fma2(q1_.x, (HV2), ACC[2]);                         \
        ACC[3] = fma2(q1_.y, (HV2), ACC[3]);                         \
    } while (0)

__global__ __launch_bounds__(NTHR, 2)
void lstm_persist(const float* __restrict__ x,
                  const float* __restrict__ W_ih1,
                  const float* __restrict__ W_hh1,
                  const float* __restrict__ b1,
                  const float* __restrict__ W_ih2,
                  const float* __restrict__ W_hh2,
                  const float* __restrict__ b2,
                  const float* __restrict__ W_lin,
                  const float* __restrict__ b_lin,
                  float* __restrict__ out)
{
    extern __shared__ float smem[];
    // smem layout (floats), 16B aligned:
    float* W1s   = smem;                 // [512][8]   k-major, slot r = 4*u+gate
    float* W2s   = W1s + HID * 8;        // [1024][8]  (k<512: W_ih2, k>=512: W_hh2)
    float* Wih1s = W2s + 2 * HID * 8;    // [8]
    float* b1s   = Wih1s + 8;            // [8]
    float* b2s   = b1s + 8;              // [8]
    float* Wlins = b2s + 8;              // [512]
    float* red   = Wlins + HID;          // [8] warp partials (pad to 64)

    const int tid = threadIdx.x;
    const int bk  = blockIdx.x;
    const int b   = tid;                 // one batch element per thread
    const int base_u = bk * UNITS;

    unsigned long long bar_target = 0;
    if (tid == 0) bar_target = *((volatile unsigned long long*)&g_epoch);

    // ---- load this block's weight slice into shared memory ----
    // local row r = 4*u + gate; global row = gate*HID + (base_u + u)
    for (int idx = tid; idx < HID * 8; idx += NTHR) {
        int k = idx >> 3, r = idx & 7;
        int row = (r & 3) * HID + (base_u + (r >> 2));
        W1s[idx] = W_hh1[row * HID + k];
    }
    for (int idx = tid; idx < 2 * HID * 8; idx += NTHR) {
        int k = idx >> 3, r = idx & 7;
        int row = (r & 3) * HID + (base_u + (r >> 2));
        W2s[idx] = (k < HID) ? W_ih2[row * HID + k]
                             : W_hh2[row * HID + (k - HID)];
    }
    if (tid < 8) {
        int r = tid;
        int row = (r & 3) * HID + (base_u + (r >> 2));
        Wih1s[r] = W_ih1[row];
        b1s[r]   = b1[row];
        b2s[r]   = b2[row];
    }
    for (int idx = tid; idx < HID; idx += NTHR) Wlins[idx] = W_lin[idx];
    const float blin = b_lin[0];

    // ---- prologue: zero initial state, transpose x to [t][b] ----
    {
        const int total = TLEN * BATCH;
        const int gsz = GRID * NTHR;
        for (int idx = bk * NTHR + tid; idx < total; idx += gsz) {
            int bb = idx >> 10;          // /TLEN
            int tt = idx & (TLEN - 1);
            g_xT[tt * BATCH + bb] = x[idx];
        }
        for (int idx = bk * NTHR + tid; idx < HID * BATCH; idx += gsz) {
            g_h1[0][idx] = 0ull;
            g_h2[0][idx] = 0ull;
        }
    }
    grid_bar(bar_target);

    float c1[UNITS], c2[UNITS];
#pragma unroll
    for (int u = 0; u < UNITS; u++) { c1[u] = 0.0f; c2[u] = 0.0f; }

    // 4 packed accumulators: acc[2u] = (i,f) of unit u, acc[2u+1] = (g,o)
    unsigned long long acc[4];

    const unsigned long long* Wih1p = (const unsigned long long*)Wih1s;
    const unsigned long long* b1p   = (const unsigned long long*)b1s;
    const unsigned long long* b2p   = (const unsigned long long*)b2s;

    for (int t = 0; t < TLEN; t++) {
        const int p = t & 1;
        const unsigned long long* __restrict__ h1p = g_h1[p];
        unsigned long long*       __restrict__ h1n = g_h1[p ^ 1];
        const unsigned long long* __restrict__ h2p = g_h2[p];
        unsigned long long*       __restrict__ h2n = g_h2[p ^ 1];

        // ---------- phase A: layer-1 gates + cell update ----------
        {
            const float xv = g_xT[t * BATCH + b];
            const unsigned long long xv2 = pack2(xv, xv);
#pragma unroll
            for (int j = 0; j < 4; j++) acc[j] = fma2(Wih1p[j], xv2, b1p[j]);

#pragma unroll 8
            for (int k = 0; k < HID; k++) {
                unsigned long long hv2 = h1p[k * BATCH + b];
                const ulonglong2* wb = (const ulonglong2*)(W1s + (k << 3));
                FMA2x4(acc, hv2, wb);
            }
#pragma unroll
            for (int u = 0; u < UNITS; u++) {
                float pi, pf, pg, po;
                unpack2(acc[2 * u + 0], pi, pf);
                unpack2(acc[2 * u + 1], pg, po);
                float ig = sigm(pi);
                float fg = sigm(pf);
                float gg = tanhf(pg);
                float og = sigm(po);
                float c  = fg * c1[u] + ig * gg;
                c1[u] = c;
                float hv = og * tanhf(c);
                h1n[(base_u + u) * BATCH + b] = pack2(hv, hv);
            }
        }

        grid_bar(bar_target);   // the only grid barrier per step

        // ---------- output for step t-1 (reads h2 produced by phase B(t-1)) ----
        if (t > 0) {
            const int bb = bk;           // one batch element per block
            const float* h2f = (const float*)h2p;
            float s = Wlins[tid]       * h2f[(tid * BATCH + bb) << 1]
                    + Wlins[tid + 256] * h2f[((tid + 256) * BATCH + bb) << 1];
#pragma unroll
            for (int o = 16; o > 0; o >>= 1)
                s += __shfl_xor_sync(0xffffffffu, s, o);
            if ((tid & 31) == 0) red[tid >> 5] = s;   // 8 warp partials
            __syncthreads();
            if (tid == 0) {
                float r = red[0] + red[1] + red[2] + red[3]
                        + red[4] + red[5] + red[6] + red[7];
                out[bb * TLEN + (t - 1)] = r + blin;
            }
        }

        // ---------- phase B: layer-2 gates + cell update ----------
        {
#pragma unroll
            for (int j = 0; j < 4; j++) acc[j] = b2p[j];

#pragma unroll 8
            for (int k = 0; k < HID; k++) {               // input = h1 (new)
                unsigned long long hv2 = h1n[k * BATCH + b];
                const ulonglong2* wb = (const ulonglong2*)(W2s + (k << 3));
                FMA2x4(acc, hv2, wb);
            }
#pragma unroll 8
            for (int k = 0; k < HID; k++) {               // recurrent = h2 (prev)
                unsigned long long hv2 = h2p[k * BATCH + b];
                const ulonglong2* wb = (const ulonglong2*)(W2s + ((HID + k) << 3));
                FMA2x4(acc, hv2, wb);
            }
#pragma unroll
            for (int u = 0; u < UNITS; u++) {
                float pi, pf, pg, po;
                unpack2(acc[2 * u + 0], pi, pf);
                unpack2(acc[2 * u + 1], pg, po);
                float ig = sigm(pi);
                float fg = sigm(pf);
                float gg = tanhf(pg);
                float og = sigm(po);
                float c  = fg * c2[u] + ig * gg;
                c2[u] = c;
                float hv = og * tanhf(c);
                h2n[(base_u + u) * BATCH + b] = pack2(hv, hv);
            }
        }
    }

    // ---------- final output (t = TLEN-1) ----------
    grid_bar(bar_target);
    {
        const float* h2f = (const float*)g_h2[0];   // TLEN even: last write buf 0
        const int bb = bk;
        float s = Wlins[tid]       * h2f[(tid * BATCH + bb) << 1]
                + Wlins[tid + 256] * h2f[((tid + 256) * BATCH + bb) << 1];
#pragma unroll
        for (int o = 16; o > 0; o >>= 1)
            s += __shfl_xor_sync(0xffffffffu, s, o);
        if ((tid & 31) == 0) red[tid >> 5] = s;
        __syncthreads();
        if (tid == 0) {
            float r = red[0] + red[1] + red[2] + red[3]
                    + red[4] + red[5] + red[6] + red[7];
            out[bb * TLEN + (TLEN - 1)] = r + blin;
        }
    }
}

extern "C" void kernel_launch(void* const* d_in, const int* in_sizes, int n_in,
                              void* d_out, int out_size)
{
    (void)in_sizes; (void)n_in; (void)out_size;
    const float* x     = (const float*)d_in[0];
    const float* W_ih1 = (const float*)d_in[1];
    const float* W_hh1 = (const float*)d_in[2];
    const float* b1    = (const float*)d_in[3];
    const float* W_ih2 = (const float*)d_in[4];
    const float* W_hh2 = (const float*)d_in[5];
    const float* b2    = (const float*)d_in[6];
    const float* W_lin = (const float*)d_in[7];
    const float* b_lin = (const float*)d_in[8];
    float* out = (float*)d_out;

    const size_t smem_bytes =
        (size_t)(HID * 8 + 2 * HID * 8 + 8 + 8 + 8 + HID + 64) * sizeof(float);

    cudaFuncSetAttribute(lstm_persist,
                         cudaFuncAttributeMaxDynamicSharedMemorySize,
                         (int)smem_bytes);

    lstm_persist<<<GRID, NTHR, smem_bytes>>>(
        x, W_ih1, W_hh1, b1, W_ih2, W_hh2, b2, W_lin, b_lin, out);
}

// round 4
// speedup vs baseline: 1.2577x; 1.2577x over previous
#include <cuda_runtime.h>

#define HID   512
#define BATCH 256
#define TLEN  1024
#define GRID  128
#define NTHR  256
#define UNITS 4          // hidden units per block per layer (128*4 = 512)
#define PF    8          // prefetch depth (= k-loop unroll body)

// Persistent device state (padded by PF*BATCH so the prefetch pipeline can
// harmlessly over-read one body past the end).
__device__ float g_h1[2][HID * BATCH + PF * BATCH];   // [k][b] transposed
__device__ float g_h2[2][HID * BATCH + PF * BATCH];
__device__ float g_xT[TLEN * BATCH];                  // x transposed to [t][b]
__device__ unsigned long long g_epoch;
__device__ unsigned g_cnt;

__device__ __forceinline__ float sigm(float v) {
    return 1.0f / (1.0f + __expf(-v));
}

// ---- f32x2 packed-math helpers (Blackwell FFMA2 path) ----
__device__ __forceinline__ unsigned long long pack2(float lo, float hi) {
    unsigned long long r;
    asm("mov.b64 %0, {%1, %2};" : "=l"(r) : "f"(lo), "f"(hi));
    return r;
}
__device__ __forceinline__ void unpack2(unsigned long long v, float& lo, float& hi) {
    asm("mov.b64 {%0, %1}, %2;" : "=f"(lo), "=f"(hi) : "l"(v));
}
__device__ __forceinline__ unsigned long long fma2(unsigned long long a,
                                                   unsigned long long b,
                                                   unsigned long long c) {
    unsigned long long d;
    asm("fma.rn.f32x2 %0, %1, %2, %3;" : "=l"(d) : "l"(a), "l"(b), "l"(c));
    return d;
}

// Grid-wide barrier: all GRID blocks co-resident (1 block/SM, 128 <= 148 SMs).
__device__ __forceinline__ void grid_bar(unsigned long long& target) {
    __threadfence();          // release
    __syncthreads();
    if (threadIdx.x == 0) {
        target += 1;
        unsigned prev = atomicAdd(&g_cnt, 1u);
        if (prev == GRID - 1) {
            g_cnt = 0;
            __threadfence();
            atomicAdd(&g_epoch, 1ull);
        } else {
            while (*((volatile unsigned long long*)&g_epoch) < target) { }
        }
        __threadfence();      // acquire
    }
    __syncthreads();
}

// 8 packed FMAs: acc[j] covers gate rows (2j, 2j+1); weights pair-packed in smem.
#define FMA2x8(ACC, HV2, WB)                                         \
    do {                                                             \
        ulonglong2 q0_ = (WB)[0], q1_ = (WB)[1];                     \
        ulonglong2 q2_ = (WB)[2], q3_ = (WB)[3];                     \
        ACC[0] = fma2(q0_.x, (HV2), ACC[0]);                         \
        ACC[1] = fma2(q0_.y, (HV2), ACC[1]);                         \
        ACC[2] = fma2(q1_.x, (HV2), ACC[2]);                         \
        ACC[3] = fma2(q1_.y, (HV2), ACC[3]);                         \
        ACC[4] = fma2(q2_.x, (HV2), ACC[4]);                         \
        ACC[5] = fma2(q2_.y, (HV2), ACC[5]);                         \
        ACC[6] = fma2(q3_.x, (HV2), ACC[6]);                         \
        ACC[7] = fma2(q3_.y, (HV2), ACC[7]);                         \
    } while (0)

// One pipelined 512-k GEMV pass: h stream prefetched one body (PF=8) ahead.
// HP = h stream base (element [k*BATCH + b]), WS = weight smem base (float*,
// 16 floats per k), ACC = 8 packed accumulators.
#define GEMV512_PIPE(ACC, HP, WS, B_)                                 \
    do {                                                              \
        float hbuf_[PF];                                              \
        _Pragma("unroll")                                             \
        for (int j_ = 0; j_ < PF; j_++)                               \
            hbuf_[j_] = (HP)[j_ * BATCH + (B_)];                      \
        for (int k0_ = 0; k0_ < HID; k0_ += PF) {                     \
            float hnext_[PF];                                         \
            _Pragma("unroll")                                         \
            for (int j_ = 0; j_ < PF; j_++)                           \
                hnext_[j_] = (HP)[(k0_ + PF + j_) * BATCH + (B_)];    \
            _Pragma("unroll")                                         \
            for (int j_ = 0; j_ < PF; j_++) {                         \
                unsigned long long hv2_ = pack2(hbuf_[j_], hbuf_[j_]);\
                const ulonglong2* wb_ =                               \
                    (const ulonglong2*)((WS) + ((k0_ + j_) << 4));    \
                FMA2x8(ACC, hv2_, wb_);                               \
            }                                                         \
            _Pragma("unroll")                                         \
            for (int j_ = 0; j_ < PF; j_++) hbuf_[j_] = hnext_[j_];   \
        }                                                             \
    } while (0)

__global__ __launch_bounds__(NTHR, 1)
void lstm_persist(const float* __restrict__ x,
                  const float* __restrict__ W_ih1,
                  const float* __restrict__ W_hh1,
                  const float* __restrict__ b1,
                  const float* __restrict__ W_ih2,
                  const float* __restrict__ W_hh2,
                  const float* __restrict__ b2,
                  const float* __restrict__ W_lin,
                  const float* __restrict__ b_lin,
                  float* __restrict__ out)
{
    extern __shared__ float smem[];
    // smem layout (floats), 16B aligned:
    float* W1s   = smem;                 // [512][16]  k-major, slot r = 4*u+gate
    float* W2s   = W1s + HID * 16;       // [1024][16] (k<512: W_ih2, k>=512: W_hh2)
    float* Wih1s = W2s + 2 * HID * 16;   // [16]
    float* b1s   = Wih1s + 16;           // [16]
    float* b2s   = b1s + 16;             // [16]
    float* Wlins = b2s + 16;             // [512]
    float* red   = Wlins + HID;          // [8] warp partials (pad 64)

    const int tid = threadIdx.x;
    const int bk  = blockIdx.x;
    const int b   = tid;                 // one batch element per thread
    const int base_u = bk * UNITS;

    unsigned long long bar_target = 0;
    if (tid == 0) bar_target = *((volatile unsigned long long*)&g_epoch);

    // ---- load this block's weight slice into shared memory ----
    // local row r = 4*u + gate; global row = gate*HID + (base_u + u)
    for (int idx = tid; idx < HID * 16; idx += NTHR) {
        int k = idx >> 4, r = idx & 15;
        int row = (r & 3) * HID + (base_u + (r >> 2));
        W1s[idx] = W_hh1[row * HID + k];
    }
    for (int idx = tid; idx < 2 * HID * 16; idx += NTHR) {
        int k = idx >> 4, r = idx & 15;
        int row = (r & 3) * HID + (base_u + (r >> 2));
        W2s[idx] = (k < HID) ? W_ih2[row * HID + k]
                             : W_hh2[row * HID + (k - HID)];
    }
    if (tid < 16) {
        int r = tid;
        int row = (r & 3) * HID + (base_u + (r >> 2));
        Wih1s[r] = W_ih1[row];
        b1s[r]   = b1[row];
        b2s[r]   = b2[row];
    }
    for (int idx = tid; idx < HID; idx += NTHR) Wlins[idx] = W_lin[idx];
    const float blin = b_lin[0];

    // ---- prologue: zero initial state (incl. padding), transpose x ----
    {
        const int total = TLEN * BATCH;
        const int gsz = GRID * NTHR;
        for (int idx = bk * NTHR + tid; idx < total; idx += gsz) {
            int bb = idx >> 10;          // /TLEN
            int tt = idx & (TLEN - 1);
            g_xT[tt * BATCH + bb] = x[idx];
        }
        for (int idx = bk * NTHR + tid; idx < (HID + PF) * BATCH; idx += gsz) {
            g_h1[0][idx] = 0.0f; g_h1[1][idx] = 0.0f;
            g_h2[0][idx] = 0.0f; g_h2[1][idx] = 0.0f;
        }
    }
    grid_bar(bar_target);

    float c1[UNITS], c2[UNITS];
#pragma unroll
    for (int u = 0; u < UNITS; u++) { c1[u] = 0.0f; c2[u] = 0.0f; }

    // 8 packed accumulators: acc[2u] = (i,f) of unit u, acc[2u+1] = (g,o)
    unsigned long long acc[8];

    const unsigned long long* Wih1p = (const unsigned long long*)Wih1s;
    const unsigned long long* b1p   = (const unsigned long long*)b1s;
    const unsigned long long* b2p   = (const unsigned long long*)b2s;

    for (int t = 0; t < TLEN; t++) {
        const int p = t & 1;
        const float* __restrict__ h1p = g_h1[p];
        float*       __restrict__ h1n = g_h1[p ^ 1];
        const float* __restrict__ h2p = g_h2[p];
        float*       __restrict__ h2n = g_h2[p ^ 1];

        // ---------- phase A: layer-1 gates + cell update ----------
        {
            const float xv = g_xT[t * BATCH + b];
            const unsigned long long xv2 = pack2(xv, xv);
#pragma unroll
            for (int j = 0; j < 8; j++) acc[j] = fma2(Wih1p[j], xv2, b1p[j]);

            GEMV512_PIPE(acc, h1p, W1s, b);

#pragma unroll
            for (int u = 0; u < UNITS; u++) {
                float pi, pf, pg, po;
                unpack2(acc[2 * u + 0], pi, pf);
                unpack2(acc[2 * u + 1], pg, po);
                float ig = sigm(pi);
                float fg = sigm(pf);
                float gg = tanhf(pg);
                float og = sigm(po);
                float c  = fg * c1[u] + ig * gg;
                c1[u] = c;
                h1n[(base_u + u) * BATCH + b] = og * tanhf(c);
            }
        }

        grid_bar(bar_target);   // the only grid barrier per step

        // ---------- output for step t-1 (reads h2 produced by phase B(t-1)) ----
        if (t > 0) {
            const int half = tid >> 7;
            const int j = tid & 127;
            const int bb = bk * 2 + half;
            float s = 0.0f;
#pragma unroll
            for (int m = 0; m < 4; m++) {
                int k = j + 128 * m;
                s += Wlins[k] * h2p[k * BATCH + bb];
            }
#pragma unroll
            for (int o = 16; o > 0; o >>= 1)
                s += __shfl_xor_sync(0xffffffffu, s, o);
            if ((tid & 31) == 0) red[tid >> 5] = s;   // 8 warp partials
            __syncthreads();
            if (j == 0) {
                float r = red[half * 4 + 0] + red[half * 4 + 1]
                        + red[half * 4 + 2] + red[half * 4 + 3];
                out[bb * TLEN + (t - 1)] = r + blin;
            }
        }

        // ---------- phase B: layer-2 gates + cell update ----------
        {
#pragma unroll
            for (int j = 0; j < 8; j++) acc[j] = b2p[j];

            GEMV512_PIPE(acc, h1n, W2s, b);               // input = h1 (new)
            GEMV512_PIPE(acc, h2p, (W2s + HID * 16), b);  // recurrent = h2 (prev)

#pragma unroll
            for (int u = 0; u < UNITS; u++) {
                float pi, pf, pg, po;
                unpack2(acc[2 * u + 0], pi, pf);
                unpack2(acc[2 * u + 1], pg, po);
                float ig = sigm(pi);
                float fg = sigm(pf);
                float gg = tanhf(pg);
                float og = sigm(po);
                float c  = fg * c2[u] + ig * gg;
                c2[u] = c;
                h2n[(base_u + u) * BATCH + b] = og * tanhf(c);
            }
        }
    }

    // ---------- final output (t = TLEN-1) ----------
    grid_bar(bar_target);
    {
        const float* __restrict__ h2f = g_h2[0];   // TLEN even: last write buf 0
        const int half = tid >> 7;
        const int j = tid & 127;
        const int bb = bk * 2 + half;
        float s = 0.0f;
#pragma unroll
        for (int m = 0; m < 4; m++) {
            int k = j + 128 * m;
            s += Wlins[k] * h2f[k * BATCH + bb];
        }
#pragma unroll
        for (int o = 16; o > 0; o >>= 1)
            s += __shfl_xor_sync(0xffffffffu, s, o);
        if ((tid & 31) == 0) red[tid >> 5] = s;
        __syncthreads();
        if (j == 0) {
            float r = red[half * 4 + 0] + red[half * 4 + 1]
                    + red[half * 4 + 2] + red[half * 4 + 3];
            out[bb * TLEN + (TLEN - 1)] = r + blin;
        }
    }
}

extern "C" void kernel_launch(void* const* d_in, const int* in_sizes, int n_in,
                              void* d_out, int out_size)
{
    (void)in_sizes; (void)n_in; (void)out_size;
    const float* x     = (const float*)d_in[0];
    const float* W_ih1 = (const float*)d_in[1];
    const float* W_hh1 = (const float*)d_in[2];
    const float* b1    = (const float*)d_in[3];
    const float* W_ih2 = (const float*)d_in[4];
    const float* W_hh2 = (const float*)d_in[5];
    const float* b2    = (const float*)d_in[6];
    const float* W_lin = (const float*)d_in[7];
    const float* b_lin = (const float*)d_in[8];
    float* out = (float*)d_out;

    const size_t smem_bytes =
        (size_t)(HID * 16 + 2 * HID * 16 + 16 + 16 + 16 + HID + 64) * sizeof(float);

    cudaFuncSetAttribute(lstm_persist,
                         cudaFuncAttributeMaxDynamicSharedMemorySize,
                         (int)smem_bytes);

    lstm_persist<<<GRID, NTHR, smem_bytes>>>(
        x, W_ih1, W_hh1, b1, W_ih2, W_hh2, b2, W_lin, b_lin, out);
}

// round 5
// speedup vs baseline: 1.2581x; 1.0003x over previous
#include <cuda_runtime.h>

#define HID   512
#define BATCH 256
#define TLEN  1024
#define GRID  128
#define NTHR  256
#define UNITS 4          // hidden units per block per layer (128*4 = 512)
#define PF    8          // prefetch depth (= k-loop unroll body)

// Persistent device state (padded by PF*BATCH so the prefetch pipeline can
// harmlessly over-read one body past the end).
__device__ float g_h1[2][HID * BATCH + PF * BATCH];   // [k][b] transposed
__device__ float g_h2[2][HID * BATCH + PF * BATCH];
__device__ float g_xT[TLEN * BATCH];                  // x transposed to [t][b]
__device__ unsigned long long g_epoch;
__device__ unsigned g_cnt;

__device__ __forceinline__ float sigm(float v) {
    return 1.0f / (1.0f + __expf(-v));
}

// ---- f32x2 packed-math helpers (Blackwell FFMA2 path) ----
__device__ __forceinline__ unsigned long long pack2(float lo, float hi) {
    unsigned long long r;
    asm("mov.b64 %0, {%1, %2};" : "=l"(r) : "f"(lo), "f"(hi));
    return r;
}
__device__ __forceinline__ void unpack2(unsigned long long v, float& lo, float& hi) {
    asm("mov.b64 {%0, %1}, %2;" : "=f"(lo), "=f"(hi) : "l"(v));
}
__device__ __forceinline__ unsigned long long fma2(unsigned long long a,
                                                   unsigned long long b,
                                                   unsigned long long c) {
    unsigned long long d;
    asm("fma.rn.f32x2 %0, %1, %2, %3;" : "=l"(d) : "l"(a), "l"(b), "l"(c));
    return d;
}

// Grid-wide barrier: all GRID blocks co-resident (1 block/SM, 128 <= 148 SMs).
__device__ __forceinline__ void grid_bar(unsigned long long& target) {
    __threadfence();          // release
    __syncthreads();
    if (threadIdx.x == 0) {
        target += 1;
        unsigned prev = atomicAdd(&g_cnt, 1u);
        if (prev == GRID - 1) {
            g_cnt = 0;
            __threadfence();
            atomicAdd(&g_epoch, 1ull);
        } else {
            while (*((volatile unsigned long long*)&g_epoch) < target) { }
        }
        __threadfence();      // acquire
    }
    __syncthreads();
}

// 8 packed FMAs: acc[j] covers gate rows (2j, 2j+1); weights pair-packed in smem.
#define FMA2x8(ACC, HV2, WB)                                         \
    do {                                                             \
        ulonglong2 q0_ = (WB)[0], q1_ = (WB)[1];                     \
        ulonglong2 q2_ = (WB)[2], q3_ = (WB)[3];                     \
        ACC[0] = fma2(q0_.x, (HV2), ACC[0]);                         \
        ACC[1] = fma2(q0_.y, (HV2), ACC[1]);                         \
        ACC[2] = fma2(q1_.x, (HV2), ACC[2]);                         \
        ACC[3] = fma2(q1_.y, (HV2), ACC[3]);                         \
        ACC[4] = fma2(q2_.x, (HV2), ACC[4]);                         \
        ACC[5] = fma2(q2_.y, (HV2), ACC[5]);                         \
        ACC[6] = fma2(q3_.x, (HV2), ACC[6]);                         \
        ACC[7] = fma2(q3_.y, (HV2), ACC[7]);                         \
    } while (0)

// One pipelined 512-k GEMV pass: h stream prefetched one body (PF=8) ahead.
// HP = h stream base (element [k*BATCH + b]), WS = weight smem base (float*,
// 16 floats per k), ACC = 8 packed accumulators.
#define GEMV512_PIPE(ACC, HP, WS, B_)                                 \
    do {                                                              \
        float hbuf_[PF];                                              \
        _Pragma("unroll")                                             \
        for (int j_ = 0; j_ < PF; j_++)                               \
            hbuf_[j_] = (HP)[j_ * BATCH + (B_)];                      \
        for (int k0_ = 0; k0_ < HID; k0_ += PF) {                     \
            float hnext_[PF];                                         \
            _Pragma("unroll")                                         \
            for (int j_ = 0; j_ < PF; j_++)                           \
                hnext_[j_] = (HP)[(k0_ + PF + j_) * BATCH + (B_)];    \
            _Pragma("unroll")                                         \
            for (int j_ = 0; j_ < PF; j_++) {                         \
                unsigned long long hv2_ = pack2(hbuf_[j_], hbuf_[j_]);\
                const ulonglong2* wb_ =                               \
                    (const ulonglong2*)((WS) + ((k0_ + j_) << 4));    \
                FMA2x8(ACC, hv2_, wb_);                               \
            }                                                         \
            _Pragma("unroll")                                         \
            for (int j_ = 0; j_ < PF; j_++) hbuf_[j_] = hnext_[j_];   \
        }                                                             \
    } while (0)

__global__ __launch_bounds__(NTHR, 1)
void lstm_persist(const float* __restrict__ x,
                  const float* __restrict__ W_ih1,
                  const float* __restrict__ W_hh1,
                  const float* __restrict__ b1,
                  const float* __restrict__ W_ih2,
                  const float* __restrict__ W_hh2,
                  const float* __restrict__ b2,
                  const float* __restrict__ W_lin,
                  const float* __restrict__ b_lin,
                  float* __restrict__ out)
{
    extern __shared__ float smem[];
    // smem layout (floats), 16B aligned:
    float* W1s   = smem;                 // [512][16]  k-major, slot r = 4*u+gate
    float* W2s   = W1s + HID * 16;       // [1024][16] (k<512: W_ih2, k>=512: W_hh2)
    float* Wih1s = W2s + 2 * HID * 16;   // [16]
    float* b1s   = Wih1s + 16;           // [16]
    float* b2s   = b1s + 16;             // [16]
    float* Wlins = b2s + 16;             // [512]
    float* red   = Wlins + HID;          // [8] warp partials (pad 64)

    const int tid = threadIdx.x;
    const int bk  = blockIdx.x;
    const int b   = tid;                 // one batch element per thread
    const int base_u = bk * UNITS;

    unsigned long long bar_target = 0;
    if (tid == 0) bar_target = *((volatile unsigned long long*)&g_epoch);

    // ---- load this block's weight slice into shared memory ----
    // local row r = 4*u + gate; global row = gate*HID + (base_u + u)
    for (int idx = tid; idx < HID * 16; idx += NTHR) {
        int k = idx >> 4, r = idx & 15;
        int row = (r & 3) * HID + (base_u + (r >> 2));
        W1s[idx] = W_hh1[row * HID + k];
    }
    for (int idx = tid; idx < 2 * HID * 16; idx += NTHR) {
        int k = idx >> 4, r = idx & 15;
        int row = (r & 3) * HID + (base_u + (r >> 2));
        W2s[idx] = (k < HID) ? W_ih2[row * HID + k]
                             : W_hh2[row * HID + (k - HID)];
    }
    if (tid < 16) {
        int r = tid;
        int row = (r & 3) * HID + (base_u + (r >> 2));
        Wih1s[r] = W_ih1[row];
        b1s[r]   = b1[row];
        b2s[r]   = b2[row];
    }
    for (int idx = tid; idx < HID; idx += NTHR) Wlins[idx] = W_lin[idx];
    const float blin = b_lin[0];

    // ---- prologue: zero initial state (incl. padding), transpose x ----
    {
        const int total = TLEN * BATCH;
        const int gsz = GRID * NTHR;
        for (int idx = bk * NTHR + tid; idx < total; idx += gsz) {
            int bb = idx >> 10;          // /TLEN
            int tt = idx & (TLEN - 1);
            g_xT[tt * BATCH + bb] = x[idx];
        }
        for (int idx = bk * NTHR + tid; idx < (HID + PF) * BATCH; idx += gsz) {
            g_h1[0][idx] = 0.0f; g_h1[1][idx] = 0.0f;
            g_h2[0][idx] = 0.0f; g_h2[1][idx] = 0.0f;
        }
    }
    grid_bar(bar_target);

    float c1[UNITS], c2[UNITS];
#pragma unroll
    for (int u = 0; u < UNITS; u++) { c1[u] = 0.0f; c2[u] = 0.0f; }

    // 8 packed accumulators: acc[2u] = (i,f) of unit u, acc[2u+1] = (g,o)
    unsigned long long acc[8];

    const unsigned long long* Wih1p = (const unsigned long long*)Wih1s;
    const unsigned long long* b1p   = (const unsigned long long*)b1s;
    const unsigned long long* b2p   = (const unsigned long long*)b2s;

    for (int t = 0; t < TLEN; t++) {
        const int p = t & 1;
        const float* __restrict__ h1p = g_h1[p];
        float*       __restrict__ h1n = g_h1[p ^ 1];
        const float* __restrict__ h2p = g_h2[p];
        float*       __restrict__ h2n = g_h2[p ^ 1];

        // ---------- phase A: layer-1 gates + cell update ----------
        {
            const float xv = g_xT[t * BATCH + b];
            const unsigned long long xv2 = pack2(xv, xv);
#pragma unroll
            for (int j = 0; j < 8; j++) acc[j] = fma2(Wih1p[j], xv2, b1p[j]);

            GEMV512_PIPE(acc, h1p, W1s, b);

#pragma unroll
            for (int u = 0; u < UNITS; u++) {
                float pi, pf, pg, po;
                unpack2(acc[2 * u + 0], pi, pf);
                unpack2(acc[2 * u + 1], pg, po);
                float ig = sigm(pi);
                float fg = sigm(pf);
                float gg = tanhf(pg);
                float og = sigm(po);
                float c  = fg * c1[u] + ig * gg;
                c1[u] = c;
                h1n[(base_u + u) * BATCH + b] = og * tanhf(c);
            }
        }

        grid_bar(bar_target);   // the only grid barrier per step

        // ---------- output for step t-1 (reads h2 produced by phase B(t-1)) ----
        if (t > 0) {
            const int half = tid >> 7;
            const int j = tid & 127;
            const int bb = bk * 2 + half;
            float s = 0.0f;
#pragma unroll
            for (int m = 0; m < 4; m++) {
                int k = j + 128 * m;
                s += Wlins[k] * h2p[k * BATCH + bb];
            }
#pragma unroll
            for (int o = 16; o > 0; o >>= 1)
                s += __shfl_xor_sync(0xffffffffu, s, o);
            if ((tid & 31) == 0) red[tid >> 5] = s;   // 8 warp partials
            __syncthreads();
            if (j == 0) {
                float r = red[half * 4 + 0] + red[half * 4 + 1]
                        + red[half * 4 + 2] + red[half * 4 + 3];
                out[bb * TLEN + (t - 1)] = r + blin;
            }
        }

        // ---------- phase B: layer-2 gates + cell update ----------
        {
#pragma unroll
            for (int j = 0; j < 8; j++) acc[j] = b2p[j];

            GEMV512_PIPE(acc, h1n, W2s, b);               // input = h1 (new)
            GEMV512_PIPE(acc, h2p, (W2s + HID * 16), b);  // recurrent = h2 (prev)

#pragma unroll
            for (int u = 0; u < UNITS; u++) {
                float pi, pf, pg, po;
                unpack2(acc[2 * u + 0], pi, pf);
                unpack2(acc[2 * u + 1], pg, po);
                float ig = sigm(pi);
                float fg = sigm(pf);
                float gg = tanhf(pg);
                float og = sigm(po);
                float c  = fg * c2[u] + ig * gg;
                c2[u] = c;
                h2n[(base_u + u) * BATCH + b] = og * tanhf(c);
            }
        }
    }

    // ---------- final output (t = TLEN-1) ----------
    grid_bar(bar_target);
    {
        const float* __restrict__ h2f = g_h2[0];   // TLEN even: last write buf 0
        const int half = tid >> 7;
        const int j = tid & 127;
        const int bb = bk * 2 + half;
        float s = 0.0f;
#pragma unroll
        for (int m = 0; m < 4; m++) {
            int k = j + 128 * m;
            s += Wlins[k] * h2f[k * BATCH + bb];
        }
#pragma unroll
        for (int o = 16; o > 0; o >>= 1)
            s += __shfl_xor_sync(0xffffffffu, s, o);
        if ((tid & 31) == 0) red[tid >> 5] = s;
        __syncthreads();
        if (j == 0) {
            float r = red[half * 4 + 0] + red[half * 4 + 1]
                    + red[half * 4 + 2] + red[half * 4 + 3];
            out[bb * TLEN + (TLEN - 1)] = r + blin;
        }
    }
}

extern "C" void kernel_launch(void* const* d_in, const int* in_sizes, int n_in,
                              void* d_out, int out_size)
{
    (void)in_sizes; (void)n_in; (void)out_size;
    const float* x     = (const float*)d_in[0];
    const float* W_ih1 = (const float*)d_in[1];
    const float* W_hh1 = (const float*)d_in[2];
    const float* b1    = (const float*)d_in[3];
    const float* W_ih2 = (const float*)d_in[4];
    const float* W_hh2 = (const float*)d_in[5];
    const float* b2    = (const float*)d_in[6];
    const float* W_lin = (const float*)d_in[7];
    const float* b_lin = (const float*)d_in[8];
    float* out = (float*)d_out;

    const size_t smem_bytes =
        (size_t)(HID * 16 + 2 * HID * 16 + 16 + 16 + 16 + HID + 64) * sizeof(float);

    cudaFuncSetAttribute(lstm_persist,
                         cudaFuncAttributeMaxDynamicSharedMemorySize,
                         (int)smem_bytes);

    lstm_persist<<<GRID, NTHR, smem_bytes>>>(
        x, W_ih1, W_hh1, b1, W_ih2, W_hh2, b2, W_lin, b_lin, out);
}